// round 5
// baseline (speedup 1.0000x reference)
#include <cuda_runtime.h>
#include <math.h>

// ---------------------------------------------------------------------------
// FraudDetectionNet fused kernel.
//
// Math: per patch p with pixels (p0,p1,p2,p3),
//   qcontrib_p = sum_m c_p[m] * |U psi|^2_m   with psi = RY-product state.
// Using cos^2(x/2)=(1+cos x)/2 etc., this equals t01^T C_p t23 with
//   b_q = (1, cos p_q, sin p_q),  t01 = b0 (x) b1,  t23 = b2 (x) b3,
//   C_p[s] = sum_m c_p[m] K[m][s],
//   K[m][s] = sum_{n,n'} (Ure[m,n]Ure[m,n'] + Uim[m,n]Uim[m,n'])
//                         * prod_q T[(n_q,n'_q)][s_q],
//   T[(0,0)]=(.5,.5,0) T[(0,1)]=T[(1,0)]=(0,0,.5) T[(1,1)]=(.5,-.5,0),
// and c_p[m] = sum_w Z[m][w] * w_cls[1 + 4p + w]  (classifier weights folded in).
// ---------------------------------------------------------------------------

#define NPATCH   196
#define CROW     12          // padded row length (9 used) for LDS.128
#define CPP      (9*CROW)    // 108 floats per patch
#define NIMG     32
#define XSTRIDE  786         // 784 + pad (even -> float2 aligned, conflict-free)
#define NTHREADS 256
#define NWARPS   8
#define SMEM_BYTES ((NPATCH*CPP + NIMG*XSTRIDE) * 4)

__device__ float g_K[16 * 81];
__device__ float g_C[NPATCH * CPP];

// ---- precompute K[m][s] from the unitary (patch-independent) --------------
__global__ void kernelK(const float* __restrict__ Ure, const float* __restrict__ Uim) {
    int m = blockIdx.x;
    __shared__ float ur[16], ui[16];
    if (threadIdx.x < 16) {
        ur[threadIdx.x] = Ure[m * 16 + threadIdx.x];
        ui[threadIdx.x] = Uim[m * 16 + threadIdx.x];
    }
    __syncthreads();
    int s = threadIdx.x;
    if (s >= 81) return;
    int s3 = s % 3; int r = s / 3;
    int s2 = r % 3; r /= 3;
    int s1 = r % 3; int s0 = r / 3;
    const float T[4][3] = {{0.5f, 0.5f, 0.f},
                           {0.f,  0.f,  0.5f},
                           {0.f,  0.f,  0.5f},
                           {0.5f, -0.5f, 0.f}};
    float acc = 0.f;
    for (int n = 0; n < 16; ++n) {
        for (int np = 0; np < 16; ++np) {
            float wgt = T[((n >> 3) & 1) * 2 + ((np >> 3) & 1)][s0]
                      * T[((n >> 2) & 1) * 2 + ((np >> 2) & 1)][s1]
                      * T[((n >> 1) & 1) * 2 + ((np >> 1) & 1)][s2]
                      * T[((n     ) & 1) * 2 + ((np     ) & 1)][s3];
            acc = fmaf(wgt, ur[n] * ur[np] + ui[n] * ui[np], acc);
        }
    }
    g_K[m * 81 + s] = acc;
}

// ---- precompute per-patch C_p (padded rows of 12) -------------------------
__global__ void kernelC(const float* __restrict__ w_cls) {
    int p = blockIdx.x;
    int t = threadIdx.x;
    __shared__ float c[16];
    if (t < 16) {
        float acc = 0.f;
#pragma unroll
        for (int w = 0; w < 4; ++w) {
            float z = 1.f - 2.f * (float)((t >> (3 - w)) & 1);  // wire 0 = MSB
            acc = fmaf(z, w_cls[1 + 4 * p + w], acc);
        }
        c[t] = acc;
    }
    __syncthreads();
    if (t < CPP) {
        int i = t / CROW, j = t % CROW;
        float v = 0.f;
        if (j < 9) {
            int s = i * 9 + j;
#pragma unroll
            for (int m = 0; m < 16; ++m) v = fmaf(c[m], g_K[m * 81 + s], v);
        }
        g_C[p * CPP + t] = v;
    }
}

// ---- main fused kernel: 32 images per block -------------------------------
__global__ void __launch_bounds__(NTHREADS, 1)
mainK(const float* __restrict__ x,
      const float* __restrict__ w_in,   const float* __restrict__ b_in,
      const float* __restrict__ scale_in, const float* __restrict__ shift_in,
      const float* __restrict__ Wc,     const float* __restrict__ bc,
      const float* __restrict__ scalec, const float* __restrict__ shiftc,
      const float* __restrict__ w_out,  const float* __restrict__ b_out,
      const float* __restrict__ w_cls,  const float* __restrict__ b_cls,
      float* __restrict__ out, int B, int L)
{
    extern __shared__ float sm[];
    float* Cs = sm;                       // NPATCH*CPP floats
    float* xs = sm + NPATCH * CPP;        // NIMG*XSTRIDE floats
    __shared__ float rq[NWARPS][33], ra[NWARPS][33], rb[NWARPS][33];

    const int tid  = threadIdx.x;
    const int w    = tid >> 5;
    const int lane = tid & 31;
    const int img_base = blockIdx.x * NIMG;
    int nimg = B - img_base;
    if (nimg > NIMG) nimg = NIMG;

    // stage C (warp-uniform reads later) and the 32 images (coalesced float4)
    for (int i = tid; i < NPATCH * CPP; i += NTHREADS) Cs[i] = g_C[i];
    const float* gx = x + (size_t)img_base * 784;
    for (int img = w; img < nimg; img += NWARPS) {
        const float4* src = (const float4*)(gx + img * 784);
        float* dst = xs + img * XSTRIDE;
        for (int k = lane; k < 196; k += 32) {
            float4 v = src[k];
            dst[4 * k + 0] = v.x; dst[4 * k + 1] = v.y;
            dst[4 * k + 2] = v.z; dst[4 * k + 3] = v.w;
        }
    }
    __syncthreads();

    float qsum = 0.f, s1 = 0.f, s2 = 0.f;
    if (lane < nimg) {
        const float* xi = xs + lane * XSTRIDE;
        const int pstart = (w * NPATCH) / NWARPS;
        const int pend   = ((w + 1) * NPATCH) / NWARPS;
        int pr = pstart / 14, pc = pstart - pr * 14;
        for (int p = pstart; p < pend; ++p) {
            int off = pr * 56 + pc * 2;
            float2 tp = *(const float2*)(xi + off);
            float2 bt = *(const float2*)(xi + off + 28);
            if (++pc == 14) { pc = 0; ++pr; }

            s1 += tp.x + tp.y + bt.x + bt.y;
            s2 = fmaf(tp.x, tp.x, fmaf(tp.y, tp.y,
                 fmaf(bt.x, bt.x, fmaf(bt.y, bt.y, s2))));

            float c0, sn0, c1, sn1, c2, sn2, c3, sn3;
            __sincosf(tp.x, &sn0, &c0);
            __sincosf(tp.y, &sn1, &c1);
            __sincosf(bt.x, &sn2, &c2);
            __sincosf(bt.y, &sn3, &c3);

            float t01[9], t23[9];
            t01[0] = 1.f;  t01[1] = c1;       t01[2] = sn1;
            t01[3] = c0;   t01[4] = c0 * c1;  t01[5] = c0 * sn1;
            t01[6] = sn0;  t01[7] = sn0 * c1; t01[8] = sn0 * sn1;
            t23[0] = 1.f;  t23[1] = c3;       t23[2] = sn3;
            t23[3] = c2;   t23[4] = c2 * c3;  t23[5] = c2 * sn3;
            t23[6] = sn2;  t23[7] = sn2 * c3; t23[8] = sn2 * sn3;

            const float4* Cp = (const float4*)(Cs + p * CPP);
            float acc = 0.f;
#pragma unroll
            for (int i = 0; i < 9; ++i) {
                float4 a  = Cp[i * 3 + 0];
                float4 b4 = Cp[i * 3 + 1];
                float4 e  = Cp[i * 3 + 2];
                float d = a.x;                      // t23[0] == 1
                d = fmaf(a.y,  t23[1], d);
                d = fmaf(a.z,  t23[2], d);
                d = fmaf(a.w,  t23[3], d);
                d = fmaf(b4.x, t23[4], d);
                d = fmaf(b4.y, t23[5], d);
                d = fmaf(b4.z, t23[6], d);
                d = fmaf(b4.w, t23[7], d);
                d = fmaf(e.x,  t23[8], d);
                acc = fmaf(t01[i], d, acc);
            }
            qsum += acc;
        }
    }

    rq[w][lane] = qsum; ra[w][lane] = s1; rb[w][lane] = s2;
    __syncthreads();

    if (tid < 32 && tid < nimg) {
        float Q = 0.f, S1 = 0.f, S2 = 0.f;
#pragma unroll
        for (int k = 0; k < NWARPS; ++k) { Q += rq[k][tid]; S1 += ra[k][tid]; S2 += rb[k][tid]; }
        float mean = S1 * (1.f / 784.f);
        float var  = (S2 - S1 * S1 * (1.f / 784.f)) * (1.f / 783.f);
        float stdv = sqrtf(fmaxf(var, 0.f));
        float h0 = tanhf(fmaf(mean, w_in[0], fmaf(stdv, w_in[1], b_in[0]))) * scale_in[0] + shift_in[0];
        float h1 = tanhf(fmaf(mean, w_in[2], fmaf(stdv, w_in[3], b_in[1]))) * scale_in[1] + shift_in[1];
        for (int i = 0; i < L; ++i) {
            float n0 = tanhf(fmaf(h0, Wc[i*4+0], fmaf(h1, Wc[i*4+1], bc[i*2+0]))) * scalec[i*2+0] + shiftc[i*2+0];
            float n1 = tanhf(fmaf(h0, Wc[i*4+2], fmaf(h1, Wc[i*4+3], bc[i*2+1]))) * scalec[i*2+1] + shiftc[i*2+1];
            h0 = n0; h1 = n1;
        }
        float cls   = fmaf(h0, w_out[0], fmaf(h1, w_out[1], b_out[0]));
        float logit = fmaf(cls, w_cls[0], Q + b_cls[0]);
        out[img_base + tid] = 1.f / (1.f + expf(-logit));
    }
}

extern "C" void kernel_launch(void* const* d_in, const int* in_sizes, int n_in,
                              void* d_out, int out_size) {
    const float* x        = (const float*)d_in[0];
    const float* w_in     = (const float*)d_in[1];
    const float* b_in     = (const float*)d_in[2];
    const float* scale_in = (const float*)d_in[3];
    const float* shift_in = (const float*)d_in[4];
    const float* Wc       = (const float*)d_in[5];
    const float* bc       = (const float*)d_in[6];
    const float* scalec   = (const float*)d_in[7];
    const float* shiftc   = (const float*)d_in[8];
    const float* w_out    = (const float*)d_in[9];
    const float* b_out    = (const float*)d_in[10];
    const float* U_re     = (const float*)d_in[11];
    const float* U_im     = (const float*)d_in[12];
    const float* w_cls    = (const float*)d_in[13];
    const float* b_cls    = (const float*)d_in[14];
    float* out = (float*)d_out;

    int B = in_sizes[0] / 784;
    int L = in_sizes[5] / 4;

    cudaFuncSetAttribute(mainK, cudaFuncAttributeMaxDynamicSharedMemorySize, SMEM_BYTES);

    kernelK<<<16, 96>>>(U_re, U_im);
    kernelC<<<NPATCH, 128>>>(w_cls);
    mainK<<<(B + NIMG - 1) / NIMG, NTHREADS, SMEM_BYTES>>>(
        x, w_in, b_in, scale_in, shift_in, Wc, bc, scalec, shiftc,
        w_out, b_out, w_cls, b_cls, out, B, L);
}

// round 7
// speedup vs baseline: 1.3760x; 1.3760x over previous
#include <cuda_runtime.h>
#include <math.h>

// ---------------------------------------------------------------------------
// FraudDetectionNet fused kernel.
//
// Per patch p: qcontrib_p = t01^T C_p t23 with b_q=(1,cos p_q,sin p_q),
// t01=b0(x)b1, t23=b2(x)b3, and C_p[s] = sum_m c_p[m] K[m][s].
// K collapsed: since each qubit's T-table has exactly 2 nonzero pair-patterns
// per s-component,
//   K[m][s] = (1/16) sum_{n=0..15} (-1)^{popc(n&neg)}
//             (Ur[m,n]Ur[m,n^mask] + Ui[m,n]Ui[m,n^mask]),
//   mask_q = (s_q==2), neg_q = (s_q==1)   (16 terms, not 256).
// c_p[m] folds Z and the classifier weights.
// ---------------------------------------------------------------------------

#define NPATCH   196
#define CROW     12          // padded row length (9 used) for LDS.128
#define CPP      (9*CROW)    // 108 floats per patch
#define NIMG     32
#define XSTRIDE  786         // 784 + pad (even -> float2 aligned)
#define NTHREADS 512
#define NWARPS   16
#define SMEM_BYTES ((NPATCH*CPP + NIMG*XSTRIDE) * 4)

__device__ float g_C[NPATCH * CPP];

// ---- fused precompute: K (collapsed form) + per-patch C -------------------
// grid = 49 blocks (4 patches each), 256 threads
__global__ void kernelPre(const float* __restrict__ Ure,
                          const float* __restrict__ Uim,
                          const float* __restrict__ w_cls) {
    __shared__ float ur[256], ui[256];
    __shared__ float Ks[16 * 81];
    __shared__ float c[4][16];
    const int t = threadIdx.x;
    const int pbase = blockIdx.x * 4;

    ur[t] = Ure[t];
    ui[t] = Uim[t];
    if (t < 64) {
        int pp = t >> 4, m = t & 15;
        const float* wp = w_cls + 1 + 4 * (pbase + pp);
        float acc = 0.f;
#pragma unroll
        for (int w = 0; w < 4; ++w)
            acc = fmaf(1.f - 2.f * (float)((m >> (3 - w)) & 1), wp[w], acc);
        c[pp][m] = acc;
    }
    __syncthreads();

    for (int e = t; e < 16 * 81; e += 256) {
        int m = e / 81, s = e - m * 81;
        int s3 = s % 3, r = s / 3;
        int s2 = r % 3; r /= 3;
        int s1 = r % 3, s0 = r / 3;
        int mask = ((int)(s0 == 2) << 3) | ((int)(s1 == 2) << 2)
                 | ((int)(s2 == 2) << 1) | (int)(s3 == 2);
        int neg  = ((int)(s0 == 1) << 3) | ((int)(s1 == 1) << 2)
                 | ((int)(s2 == 1) << 1) | (int)(s3 == 1);
        const float* urm = ur + m * 16;
        const float* uim = ui + m * 16;
        float acc = 0.f;
#pragma unroll
        for (int n = 0; n < 16; ++n) {
            float v = urm[n] * urm[n ^ mask] + uim[n] * uim[n ^ mask];
            acc += (__popc(n & neg) & 1) ? -v : v;
        }
        Ks[e] = acc * 0.0625f;
    }
    __syncthreads();

    for (int e = t; e < 4 * CPP; e += 256) {
        int pp = e / CPP, r = e - pp * CPP;
        int i = r / CROW, j = r - i * CROW;
        float v = 0.f;
        if (j < 9) {
            int s = i * 9 + j;
#pragma unroll
            for (int m = 0; m < 16; ++m) v = fmaf(c[pp][m], Ks[m * 81 + s], v);
        }
        g_C[(pbase + pp) * CPP + r] = v;
    }
}

// ---- main fused kernel: 32 images per block, 16 warps ---------------------
__global__ void __launch_bounds__(NTHREADS, 1)
mainK(const float* __restrict__ x,
      const float* __restrict__ w_in,   const float* __restrict__ b_in,
      const float* __restrict__ scale_in, const float* __restrict__ shift_in,
      const float* __restrict__ Wc,     const float* __restrict__ bc,
      const float* __restrict__ scalec, const float* __restrict__ shiftc,
      const float* __restrict__ w_out,  const float* __restrict__ b_out,
      const float* __restrict__ w_cls,  const float* __restrict__ b_cls,
      float* __restrict__ out, int B, int L)
{
    extern __shared__ float sm[];
    float* Cs = sm;                       // NPATCH*CPP floats
    float* xs = sm + NPATCH * CPP;        // NIMG*XSTRIDE floats
    __shared__ float rq[NWARPS][33], ra[NWARPS][33], rb[NWARPS][33];

    const int tid  = threadIdx.x;
    const int w    = tid >> 5;
    const int lane = tid & 31;
    const int img_base = blockIdx.x * NIMG;
    int nimg = B - img_base;
    if (nimg > NIMG) nimg = NIMG;

    // stage C (float4, CPP divisible by 4) and the images (coalesced float4)
    {
        const float4* gc4 = (const float4*)g_C;
        float4* cs4 = (float4*)Cs;
        for (int i = tid; i < NPATCH * CPP / 4; i += NTHREADS) cs4[i] = gc4[i];
    }
    const float* gx = x + (size_t)img_base * 784;
    for (int img = w; img < nimg; img += NWARPS) {
        const float4* src = (const float4*)(gx + img * 784);
        float* dst = xs + img * XSTRIDE;
        for (int k = lane; k < 196; k += 32) {
            float4 v = src[k];
            dst[4 * k + 0] = v.x; dst[4 * k + 1] = v.y;
            dst[4 * k + 2] = v.z; dst[4 * k + 3] = v.w;
        }
    }
    __syncthreads();

    float qsum = 0.f, s1 = 0.f, s2 = 0.f;
    if (lane < nimg) {
        const float* xi = xs + lane * XSTRIDE;
        const int pstart = (w * NPATCH) / NWARPS;
        const int pend   = ((w + 1) * NPATCH) / NWARPS;
        int pr = pstart / 14, pc = pstart - pr * 14;
        for (int p = pstart; p < pend; ++p) {
            int off = pr * 56 + pc * 2;
            float2 tp = *(const float2*)(xi + off);
            float2 bt = *(const float2*)(xi + off + 28);
            if (++pc == 14) { pc = 0; ++pr; }

            s1 += tp.x + tp.y + bt.x + bt.y;
            s2 = fmaf(tp.x, tp.x, fmaf(tp.y, tp.y,
                 fmaf(bt.x, bt.x, fmaf(bt.y, bt.y, s2))));

            float c0v, s0v, c1v, s1v, c2v, s2v, c3v, s3v;
            __sincosf(tp.x, &s0v, &c0v);
            __sincosf(tp.y, &s1v, &c1v);
            __sincosf(bt.x, &s2v, &c2v);
            __sincosf(bt.y, &s3v, &c3v);

            // t23 = [1, c3, s3, c2, c2c3, c2s3, s2, s2c3, s2s3]
            float c2c3 = c2v * c3v, c2s3 = c2v * s3v;
            float s2c3 = s2v * c3v, s2s3 = s2v * s3v;

            const float4* Cp = (const float4*)(Cs + p * CPP);
            float d[9];
#pragma unroll
            for (int i = 0; i < 9; ++i) {
                float4 a  = Cp[i * 3 + 0];
                float4 b4 = Cp[i * 3 + 1];
                float4 e4 = Cp[i * 3 + 2];
                float dd = a.x;                    // t23[0] == 1
                dd = fmaf(a.y,  c3v,  dd);
                dd = fmaf(a.z,  s3v,  dd);
                dd = fmaf(a.w,  c2v,  dd);
                dd = fmaf(b4.x, c2c3, dd);
                dd = fmaf(b4.y, c2s3, dd);
                dd = fmaf(b4.z, s2v,  dd);
                dd = fmaf(b4.w, s2c3, dd);
                dd = fmaf(e4.x, s2s3, dd);
                d[i] = dd;
            }
            // acc = sum_i t01[i] d[i], t01 = (1,c1,s1)(x)... nested:
            float e0 = fmaf(d[2], s1v, fmaf(d[1], c1v, d[0]));
            float e1 = fmaf(d[5], s1v, fmaf(d[4], c1v, d[3]));
            float e2 = fmaf(d[8], s1v, fmaf(d[7], c1v, d[6]));
            qsum = fmaf(e2, s0v, fmaf(e1, c0v, e0 + qsum));
        }
    }

    rq[w][lane] = qsum; ra[w][lane] = s1; rb[w][lane] = s2;
    __syncthreads();

    if (tid < 32 && tid < nimg) {
        float Q = 0.f, S1 = 0.f, S2 = 0.f;
#pragma unroll
        for (int k = 0; k < NWARPS; ++k) { Q += rq[k][tid]; S1 += ra[k][tid]; S2 += rb[k][tid]; }
        float mean = S1 * (1.f / 784.f);
        float var  = (S2 - S1 * S1 * (1.f / 784.f)) * (1.f / 783.f);
        float stdv = sqrtf(fmaxf(var, 0.f));
        float h0 = tanhf(fmaf(mean, w_in[0], fmaf(stdv, w_in[1], b_in[0]))) * scale_in[0] + shift_in[0];
        float h1 = tanhf(fmaf(mean, w_in[2], fmaf(stdv, w_in[3], b_in[1]))) * scale_in[1] + shift_in[1];
        for (int i = 0; i < L; ++i) {
            float n0 = tanhf(fmaf(h0, Wc[i*4+0], fmaf(h1, Wc[i*4+1], bc[i*2+0]))) * scalec[i*2+0] + shiftc[i*2+0];
            float n1 = tanhf(fmaf(h0, Wc[i*4+2], fmaf(h1, Wc[i*4+3], bc[i*2+1]))) * scalec[i*2+1] + shiftc[i*2+1];
            h0 = n0; h1 = n1;
        }
        float cls   = fmaf(h0, w_out[0], fmaf(h1, w_out[1], b_out[0]));
        float logit = fmaf(cls, w_cls[0], Q + b_cls[0]);
        out[img_base + tid] = 1.f / (1.f + expf(-logit));
    }
}

extern "C" void kernel_launch(void* const* d_in, const int* in_sizes, int n_in,
                              void* d_out, int out_size) {
    const float* x        = (const float*)d_in[0];
    const float* w_in     = (const float*)d_in[1];
    const float* b_in     = (const float*)d_in[2];
    const float* scale_in = (const float*)d_in[3];
    const float* shift_in = (const float*)d_in[4];
    const float* Wc       = (const float*)d_in[5];
    const float* bc       = (const float*)d_in[6];
    const float* scalec   = (const float*)d_in[7];
    const float* shiftc   = (const float*)d_in[8];
    const float* w_out    = (const float*)d_in[9];
    const float* b_out    = (const float*)d_in[10];
    const float* U_re     = (const float*)d_in[11];
    const float* U_im     = (const float*)d_in[12];
    const float* w_cls    = (const float*)d_in[13];
    const float* b_cls    = (const float*)d_in[14];
    float* out = (float*)d_out;

    int B = in_sizes[0] / 784;
    int L = in_sizes[5] / 4;

    cudaFuncSetAttribute(mainK, cudaFuncAttributeMaxDynamicSharedMemorySize, SMEM_BYTES);

    kernelPre<<<NPATCH / 4, 256>>>(U_re, U_im, w_cls);
    mainK<<<(B + NIMG - 1) / NIMG, NTHREADS, SMEM_BYTES>>>(
        x, w_in, b_in, scale_in, shift_in, Wc, bc, scalec, shiftc,
        w_out, b_out, w_cls, b_cls, out, B, L);
}

// round 8
// speedup vs baseline: 1.5571x; 1.1317x over previous
#include <cuda_runtime.h>
#include <math.h>

// ---------------------------------------------------------------------------
// FraudDetectionNet fused kernel.
//
// Per patch p: qcontrib_p = t01^T C_p t23 with b_q=(1,cos p_q,sin p_q),
// t01=b0(x)b1, t23=b2(x)b3, and C_p[s] = sum_m c_p[m] K[m][s].
// K collapsed to 16 XOR/sign terms per element:
//   K[m][s] = (1/16) sum_{n} (-1)^{popc(n&neg)}
//             (Ur[m,n]Ur[m,n^mask] + Ui[m,n]Ui[m,n^mask]),
//   mask_q=(s_q==2), neg_q=(s_q==1).
// c_p[m] folds Z and the classifier weights.
// C stored flat: 81 floats per patch padded to 84 (21 float4).
// ---------------------------------------------------------------------------

#define NPATCH   196
#define CPP      84          // 81 used + 3 pad -> 21 float4 per patch
#define NIMG     32
#define XSTRIDE  786         // 784 + pad (even -> LDS.64 aligned, conflict-free)
#define NTHREADS 1024
#define NWARPS   32
#define SMEM_BYTES ((NPATCH*CPP + NIMG*XSTRIDE) * 4)

__device__ float g_C[NPATCH * CPP];

// ---- fused precompute: K (collapsed form) + per-patch C -------------------
__global__ void kernelPre(const float* __restrict__ Ure,
                          const float* __restrict__ Uim,
                          const float* __restrict__ w_cls) {
    __shared__ float ur[256], ui[256];
    __shared__ float Ks[16 * 81];
    __shared__ float c[4][16];
    const int t = threadIdx.x;
    const int pbase = blockIdx.x * 4;

    ur[t] = Ure[t];
    ui[t] = Uim[t];
    if (t < 64) {
        int pp = t >> 4, m = t & 15;
        const float* wp = w_cls + 1 + 4 * (pbase + pp);
        float acc = 0.f;
#pragma unroll
        for (int w = 0; w < 4; ++w)
            acc = fmaf(1.f - 2.f * (float)((m >> (3 - w)) & 1), wp[w], acc);
        c[pp][m] = acc;
    }
    __syncthreads();

    for (int e = t; e < 16 * 81; e += 256) {
        int m = e / 81, s = e - m * 81;
        int s3 = s % 3, r = s / 3;
        int s2 = r % 3; r /= 3;
        int s1 = r % 3, s0 = r / 3;
        int mask = ((int)(s0 == 2) << 3) | ((int)(s1 == 2) << 2)
                 | ((int)(s2 == 2) << 1) | (int)(s3 == 2);
        int neg  = ((int)(s0 == 1) << 3) | ((int)(s1 == 1) << 2)
                 | ((int)(s2 == 1) << 1) | (int)(s3 == 1);
        const float* urm = ur + m * 16;
        const float* uim = ui + m * 16;
        float acc = 0.f;
#pragma unroll
        for (int n = 0; n < 16; ++n) {
            float v = urm[n] * urm[n ^ mask] + uim[n] * uim[n ^ mask];
            acc += (__popc(n & neg) & 1) ? -v : v;
        }
        Ks[e] = acc * 0.0625f;
    }
    __syncthreads();

    for (int e = t; e < 4 * CPP; e += 256) {
        int pp = e / CPP, k = e - pp * CPP;
        float v = 0.f;
        if (k < 81) {
#pragma unroll
            for (int m = 0; m < 16; ++m) v = fmaf(c[pp][m], Ks[m * 81 + k], v);
        }
        g_C[(pbase + pp) * CPP + k] = v;
    }
}

// ---- main fused kernel: 32 images per block, 32 warps ---------------------
__global__ void __launch_bounds__(NTHREADS, 1)
mainK(const float* __restrict__ x,
      const float* __restrict__ w_in,   const float* __restrict__ b_in,
      const float* __restrict__ scale_in, const float* __restrict__ shift_in,
      const float* __restrict__ Wc,     const float* __restrict__ bc,
      const float* __restrict__ scalec, const float* __restrict__ shiftc,
      const float* __restrict__ w_out,  const float* __restrict__ b_out,
      const float* __restrict__ w_cls,  const float* __restrict__ b_cls,
      float* __restrict__ out, int B, int L)
{
    extern __shared__ float sm[];
    float* Cs = sm;                       // NPATCH*CPP floats
    float* xs = sm + NPATCH * CPP;        // NIMG*XSTRIDE floats
    __shared__ float rq[NWARPS][33];
    __shared__ float sS1[NIMG], sS2[NIMG];

    const int tid  = threadIdx.x;
    const int w    = tid >> 5;
    const int lane = tid & 31;
    const int img_base = blockIdx.x * NIMG;
    int nimg = B - img_base;
    if (nimg > NIMG) nimg = NIMG;

    // stage C (float4, CPP divisible by 4)
    {
        const float4* gc4 = (const float4*)g_C;
        float4* cs4 = (float4*)Cs;
        for (int i = tid; i < NPATCH * CPP / 4; i += NTHREADS) cs4[i] = gc4[i];
    }
    // stage images: warp w handles image w; fold mean/std stats in here
    if (w < nimg) {
        const float4* src = (const float4*)(x + (size_t)(img_base + w) * 784);
        float* dst = xs + w * XSTRIDE;
        float ls1 = 0.f, ls2 = 0.f;
        for (int k = lane; k < 196; k += 32) {
            float4 v = src[k];
            dst[4 * k + 0] = v.x; dst[4 * k + 1] = v.y;
            dst[4 * k + 2] = v.z; dst[4 * k + 3] = v.w;
            ls1 += (v.x + v.y) + (v.z + v.w);
            ls2 = fmaf(v.x, v.x, fmaf(v.y, v.y,
                  fmaf(v.z, v.z, fmaf(v.w, v.w, ls2))));
        }
#pragma unroll
        for (int o = 16; o > 0; o >>= 1) {
            ls1 += __shfl_down_sync(0xffffffffu, ls1, o);
            ls2 += __shfl_down_sync(0xffffffffu, ls2, o);
        }
        if (lane == 0) { sS1[w] = ls1; sS2[w] = ls2; }
    }
    __syncthreads();

    float qsum = 0.f;
    if (lane < nimg) {
        const float* xi = xs + lane * XSTRIDE;
        const int pstart = (w * NPATCH) / NWARPS;
        const int pend   = ((w + 1) * NPATCH) / NWARPS;
        int pr = pstart / 14, pc = pstart - pr * 14;
        for (int p = pstart; p < pend; ++p) {
            int off = pr * 56 + pc * 2;
            float2 tp = *(const float2*)(xi + off);
            float2 bt = *(const float2*)(xi + off + 28);
            if (++pc == 14) { pc = 0; ++pr; }

            float c0v, s0v, c1v, s1v, c2v, s2v, c3v, s3v;
            __sincosf(tp.x, &s0v, &c0v);
            __sincosf(tp.y, &s1v, &c1v);
            __sincosf(bt.x, &s2v, &c2v);
            __sincosf(bt.y, &s3v, &c3v);

            // t23 = [1, c3, s3, c2, c2c3, c2s3, s2, s2c3, s2s3]
            float t23a[9];
            t23a[0] = 1.f;
            t23a[1] = c3v;        t23a[2] = s3v;
            t23a[3] = c2v;        t23a[4] = c2v * c3v;
            t23a[5] = c2v * s3v;  t23a[6] = s2v;
            t23a[7] = s2v * c3v;  t23a[8] = s2v * s3v;

            const float4* Cp4 = (const float4*)(Cs + p * CPP);
            float d[9];
#pragma unroll
            for (int q = 0; q < 21; ++q) {
                float4 f = Cp4[q];
#pragma unroll
                for (int u = 0; u < 4; ++u) {
                    int k = 4 * q + u;
                    if (k >= 81) break;
                    float v = (u == 0) ? f.x : (u == 1) ? f.y : (u == 2) ? f.z : f.w;
                    int i = k / 9, j = k - 9 * i;
                    if (j == 0) d[i] = v;
                    else        d[i] = fmaf(v, t23a[j], d[i]);
                }
            }
            // acc = sum_i t01[i] d[i], t01 = (1,c0,s0)(x)(1,c1,s1) nested:
            float e0 = fmaf(d[2], s1v, fmaf(d[1], c1v, d[0]));
            float e1 = fmaf(d[5], s1v, fmaf(d[4], c1v, d[3]));
            float e2 = fmaf(d[8], s1v, fmaf(d[7], c1v, d[6]));
            qsum = fmaf(e2, s0v, fmaf(e1, c0v, e0 + qsum));
        }
    }

    rq[w][lane] = qsum;
    __syncthreads();

    if (tid < 32 && tid < nimg) {
        float Q = 0.f;
#pragma unroll
        for (int k = 0; k < NWARPS; ++k) Q += rq[k][tid];
        float S1 = sS1[tid], S2 = sS2[tid];
        float mean = S1 * (1.f / 784.f);
        float var  = (S2 - S1 * S1 * (1.f / 784.f)) * (1.f / 783.f);
        float stdv = sqrtf(fmaxf(var, 0.f));
        float h0 = tanhf(fmaf(mean, w_in[0], fmaf(stdv, w_in[1], b_in[0]))) * scale_in[0] + shift_in[0];
        float h1 = tanhf(fmaf(mean, w_in[2], fmaf(stdv, w_in[3], b_in[1]))) * scale_in[1] + shift_in[1];
        for (int i = 0; i < L; ++i) {
            float n0 = tanhf(fmaf(h0, Wc[i*4+0], fmaf(h1, Wc[i*4+1], bc[i*2+0]))) * scalec[i*2+0] + shiftc[i*2+0];
            float n1 = tanhf(fmaf(h0, Wc[i*4+2], fmaf(h1, Wc[i*4+3], bc[i*2+1]))) * scalec[i*2+1] + shiftc[i*2+1];
            h0 = n0; h1 = n1;
        }
        float cls   = fmaf(h0, w_out[0], fmaf(h1, w_out[1], b_out[0]));
        float logit = fmaf(cls, w_cls[0], Q + b_cls[0]);
        out[img_base + tid] = 1.f / (1.f + expf(-logit));
    }
}

extern "C" void kernel_launch(void* const* d_in, const int* in_sizes, int n_in,
                              void* d_out, int out_size) {
    const float* x        = (const float*)d_in[0];
    const float* w_in     = (const float*)d_in[1];
    const float* b_in     = (const float*)d_in[2];
    const float* scale_in = (const float*)d_in[3];
    const float* shift_in = (const float*)d_in[4];
    const float* Wc       = (const float*)d_in[5];
    const float* bc       = (const float*)d_in[6];
    const float* scalec   = (const float*)d_in[7];
    const float* shiftc   = (const float*)d_in[8];
    const float* w_out    = (const float*)d_in[9];
    const float* b_out    = (const float*)d_in[10];
    const float* U_re     = (const float*)d_in[11];
    const float* U_im     = (const float*)d_in[12];
    const float* w_cls    = (const float*)d_in[13];
    const float* b_cls    = (const float*)d_in[14];
    float* out = (float*)d_out;

    int B = in_sizes[0] / 784;
    int L = in_sizes[5] / 4;

    cudaFuncSetAttribute(mainK, cudaFuncAttributeMaxDynamicSharedMemorySize, SMEM_BYTES);

    kernelPre<<<NPATCH / 4, 256>>>(U_re, U_im, w_cls);
    mainK<<<(B + NIMG - 1) / NIMG, NTHREADS, SMEM_BYTES>>>(
        x, w_in, b_in, scale_in, shift_in, Wc, bc, scalec, shiftc,
        w_out, b_out, w_cls, b_cls, out, B, L);
}